// round 16
// baseline (speedup 1.0000x reference)
#include <cuda_runtime.h>
#include <cuda_fp16.h>
#include <cstdint>
#include <math.h>

// Problem: B=1, N=256, O=16, C=64, BASIS=32, WIDEN=4
// h[m,o,c] = sum_{n,s} kb[m,n,o,s] * x[n,o,c] * Ws[s,c]   (fp16 m16n8k16 mma, fp32 acc)
// then fiber conv over o with rk = fkb@Wr, +bias, LN, MLP(gelu), +x residual.
//
// R16: conv at 512 threads/CTA (16 warps, m16 x n32 warp tiles) to double resident
// warps/SM at constant smem; tail = R14 (grid 256 x 512), unchanged.

#define KS 8
#define NT 32
#define AST 40                    // A smem row stride (fp32 words)
#define BSTH 20                   // B smem row stride (half2 words)
#define NSTG 3                    // A pipeline stages
#define A_STAGE (128 * AST * 4)   // 20480 B per A stage (m-tile 128)
#define B_BUF   (64 * BSTH * 4)   // 5120 B per B buffer
#define B_OFF   (NSTG * A_STAGE)  // 61440
#define XS_OFF  (B_OFF + 2 * B_BUF)     // 71680
#define SMEMSZ  (XS_OFF + 4 * 64 * 4)   // 72704

__device__ float g_rk[16 * 16 * 64];
__device__ float g_h1[KS][256 * 16 * 64];

// ------------------------- helpers ------------------------------------------------
__device__ __forceinline__ uint32_t smem_u32(const void* p) {
    uint32_t a;
    asm("{ .reg .u64 t; cvta.to.shared.u64 t, %1; cvt.u32.u64 %0, t; }" : "=r"(a) : "l"(p));
    return a;
}
__device__ __forceinline__ void cpa16(uint32_t smemdst, const void* gsrc) {
    asm volatile("cp.async.cg.shared.global [%0], [%1], 16;" :: "r"(smemdst), "l"(gsrc));
}
__device__ __forceinline__ uint32_t packh2(float lo, float hi) {
    __half2 h = __floats2half2_rn(lo, hi);
    return *(uint32_t*)&h;
}
__device__ __forceinline__ void mma16(float* acc,
                                      uint32_t a0, uint32_t a1, uint32_t a2, uint32_t a3,
                                      uint32_t b0, uint32_t b1) {
    asm volatile(
        "mma.sync.aligned.m16n8k16.row.col.f32.f16.f16.f32 "
        "{%0,%1,%2,%3}, {%4,%5,%6,%7}, {%8,%9}, {%0,%1,%2,%3};"
        : "+f"(acc[0]), "+f"(acc[1]), "+f"(acc[2]), "+f"(acc[3])
        : "r"(a0), "r"(a1), "r"(a2), "r"(a3), "r"(b0), "r"(b1));
}
__device__ __forceinline__ float tanh_ap(float x) {
    float y;
    asm("tanh.approx.f32 %0, %1;" : "=f"(y) : "f"(x));
    return y;
}
__device__ __forceinline__ float gelu_f(float z) {
    float t = 0.7978845608028654f * (z + 0.044715f * z * z * z);
    return 0.5f * z * (1.0f + tanh_ap(t));
}

// ------------------------- kernel 1: big conv GEMM + folded rotk ------------------
// grid (2, 16, 9), 512 threads: m-tile 128, o, k-split of 32 n-points; z==8 rotk.
// Warp tiling m16 x n32 (8 m-warps x 2 n-warps). 3-stage cp.async, lookahead 2.
__global__ __launch_bounds__(512, 2) void conv_kernel(const float* __restrict__ x,
                                                      const float* __restrict__ kb,
                                                      const float* __restrict__ Wsp,
                                                      const float* __restrict__ fkb,
                                                      const float* __restrict__ Wr) {
    if (blockIdx.z == 8) {
        int id = blockIdx.x * 16 + blockIdx.y;   // 0..31
        for (int idx = threadIdx.x; idx < 512; idx += 512) {
            int po = id * 8 + (idx >> 6), c = idx & 63;
            float acc = 0.f;
#pragma unroll
            for (int s = 0; s < 32; s++) acc += __ldg(&fkb[po * 32 + s]) * __ldg(&Wr[s * 64 + c]);
            g_rk[po * 64 + c] = acc;
        }
        return;
    }

    extern __shared__ char smem[];
    const uint32_t sbase = smem_u32(smem);
    float*    sA = (float*)smem;                 // [NSTG][128][AST] fp32
    uint32_t* sB = (uint32_t*)(smem + B_OFF);    // [2][64][BSTH] half2
    float*    xs = (float*)(smem + XS_OFF);      // [4][64] per-stage x rows

    const int tid  = threadIdx.x;
    const int w    = tid >> 5;        // 0..15
    const int lane = tid & 31;
    const int g    = lane >> 2;
    const int tq   = lane & 3;
    const int mw   = w >> 1;          // m16 block (0..7)
    const int nw   = w & 1;           // n32 block (0..1)
    const int m0   = blockIdx.x * 128;
    const int o    = blockIdx.y;
    const int ks   = blockIdx.z;
    const int n0   = ks * 32;

    auto prefetchA = [&](int t) {
        const int n = n0 + t;
        const uint32_t abase = sbase + (t % NSTG) * A_STAGE;
        const float* srcb = kb + (size_t)m0 * 131072 + (size_t)n * 512 + o * 32;
#pragma unroll
        for (int h = 0; h < 2; h++) {
            int q = tid + h * 512;           // 0..1023
            int r = q >> 3, j = q & 7;
            cpa16(abase + (uint32_t)(r * AST + j * 4) * 4,
                  srcb + (size_t)r * 131072 + j * 4);
        }
    };
    auto prefetchX = [&](int t) {
        if (tid < 16)
            cpa16(sbase + XS_OFF + (t & 3) * 256 + tid * 16,
                  x + ((size_t)(n0 + t) * 16 + o) * 64 + tid * 4);
    };

    prefetchA(0); prefetchX(0); prefetchX(1);
    asm volatile("cp.async.commit_group;" ::: "memory");
    prefetchA(1); prefetchX(2);
    asm volatile("cp.async.commit_group;" ::: "memory");

    // B-build: 512 threads, each packs 4 k-values for one channel.
    const int bc = tid >> 3, bq0 = (tid & 7) * 4;
    float ws[4];
#pragma unroll
    for (int i = 0; i < 4; i++) ws[i] = __ldg(&Wsp[(bq0 + i) * 64 + bc]);

    auto buildB = [&](int buf, int t) {
        float xv = xs[(t & 3) * 64 + bc];
        uint32_t* dst = &sB[buf * (64 * BSTH) + bc * BSTH + (bq0 >> 1)];
        uint2 v0;
        v0.x = packh2(xv * ws[0], xv * ws[1]);
        v0.y = packh2(xv * ws[2], xv * ws[3]);
        *(uint2*)dst = v0;
    };

    asm volatile("cp.async.wait_group 1;" ::: "memory");
    __syncthreads();
    buildB(0, 0);

    float acc[4][4];   // [n8 sub][frag]
#pragma unroll
    for (int ni = 0; ni < 4; ni++)
#pragma unroll
        for (int i = 0; i < 4; i++) acc[ni][i] = 0.f;

    for (int t = 0; t < NT; t++) {
        asm volatile("cp.async.wait_group 1;" ::: "memory");
        __syncthreads();

        if (t + 2 < NT) prefetchA(t + 2);
        if (t + 3 < NT) prefetchX(t + 3);
        asm volatile("cp.async.commit_group;" ::: "memory");
        if (t + 1 < NT) buildB((t + 1) & 1, t + 1);

        const float*    At  = sA + (t % NSTG) * (128 * AST);
        const uint32_t* BTh = sB + (t & 1) * (64 * BSTH);
#pragma unroll
        for (int step = 0; step < 2; step++) {
            const int k0 = step * 16;
            const float* rp0 = &At[(mw * 16 + g) * AST + k0 + 2 * tq];
            const float* rp1 = rp0 + 8 * AST;
            float2 p0 = *(const float2*)rp0;
            float2 p1 = *(const float2*)rp1;
            float2 p2 = *(const float2*)(rp0 + 8);
            float2 p3 = *(const float2*)(rp1 + 8);
            uint32_t a0 = packh2(p0.x, p0.y);
            uint32_t a1 = packh2(p1.x, p1.y);
            uint32_t a2 = packh2(p2.x, p2.y);
            uint32_t a3 = packh2(p3.x, p3.y);
#pragma unroll
            for (int ni = 0; ni < 4; ni++) {
                const int col = nw * 32 + ni * 8 + g;
                uint32_t b0 = BTh[col * BSTH + (k0 >> 1) + tq];
                uint32_t b1 = BTh[col * BSTH + (k0 >> 1) + tq + 4];
                mma16(acc[ni], a0, a1, a2, a3, b0, b1);
            }
        }
    }

    // epilogue: partials. D frag: c0=(g,2tq) c1=+1 c2=(g+8,2tq) c3=+1
    {
        const int mr = m0 + mw * 16 + g;
        float* dst0 = g_h1[ks] + ((size_t)mr * 16 + o) * 64 + nw * 32 + 2 * tq;
        float* dst1 = dst0 + (size_t)8 * 16 * 64;
#pragma unroll
        for (int ni = 0; ni < 4; ni++) {
            float2 v0 = {acc[ni][0], acc[ni][1]};
            float2 v1 = {acc[ni][2], acc[ni][3]};
            *(float2*)(dst0 + ni * 8) = v0;
            *(float2*)(dst1 + ni * 8) = v1;
        }
    }
}

// ------------------------- kernel 2: fused tail (grid 256 x 512 threads) ----------
// one block per m (16 p-rows). partial-sum + fiber conv + LN + MLP + residual.
__global__ __launch_bounds__(512) void tail_kernel(const float* __restrict__ x,
                                                   const float* __restrict__ cb,
                                                   const float* __restrict__ lns,
                                                   const float* __restrict__ lnb,
                                                   const float* __restrict__ W1,
                                                   const float* __restrict__ b1,
                                                   const float* __restrict__ W2,
                                                   const float* __restrict__ b2,
                                                   float* __restrict__ out) {
    __shared__ __align__(16) float hs[1024];       // summed conv [16 o][64 c]
    __shared__ __align__(16) float v16[16 * 64];   // post-LN rows
    __shared__ __align__(16) float u16[16 * 260];  // hidden (padded)
    __shared__ __align__(16) float pp[4][1024];    // GEMM2 partials [kq][row*64+c]

    const int tid = threadIdx.x;
    const int m   = blockIdx.x;

    // 1) sum KS k-split partials: 512 float2, one per thread
    {
        float2 a = ((const float2*)g_h1[0])[m * 512 + tid];
#pragma unroll
        for (int q = 1; q < KS; q++) {
            float2 b = ((const float2*)g_h1[q])[m * 512 + tid];
            a.x += b.x; a.y += b.y;
        }
        ((float2*)hs)[tid] = a;
    }
    __syncthreads();

    // 2) fiber conv + bias + LN; one warp per row (p = tid>>5), 2 channels/lane
    {
        const int p  = tid >> 5;          // 0..15
        const int l  = tid & 31;
        const int c0 = l * 2;
        float2 hv;
        hv.x = __ldg(&cb[c0]);
        hv.y = __ldg(&cb[c0 + 1]);
#pragma unroll
        for (int oo = 0; oo < 16; oo++) {
            float2 h2 = *(const float2*)&hs[oo * 64 + c0];
            float2 r2 = __ldg((const float2*)&g_rk[(p * 16 + oo) * 64 + c0]);
            hv.x += h2.x * r2.x;
            hv.y += h2.y * r2.y;
        }
        float s = hv.x + hv.y;
#pragma unroll
        for (int d = 1; d < 32; d <<= 1) s += __shfl_xor_sync(0xffffffffu, s, d);
        float mu = s * (1.f / 64.f);
        float d0 = hv.x - mu, d1 = hv.y - mu;
        float ss = d0 * d0 + d1 * d1;
#pragma unroll
        for (int d = 1; d < 32; d <<= 1) ss += __shfl_xor_sync(0xffffffffu, ss, d);
        float rs = rsqrtf(ss * (1.f / 64.f) + 1e-6f);
        float2 ov;
        ov.x = d0 * rs * __ldg(&lns[c0])     + __ldg(&lnb[c0]);
        ov.y = d1 * rs * __ldg(&lns[c0 + 1]) + __ldg(&lnb[c0 + 1]);
        *(float2*)&v16[p * 64 + c0] = ov;
    }
    __syncthreads();

    // 3) GEMM1 (16x64 @ 64x256) + gelu: 2 rows x 4 cols per thread, k pairs.
    {
        const int r0 = (tid >> 6) * 2;       // 0..14
        const int j0 = (tid & 63) * 4;
        float acc[2][4];
#pragma unroll
        for (int i = 0; i < 2; i++)
#pragma unroll
            for (int j = 0; j < 4; j++) acc[i][j] = 0.f;
#pragma unroll 4
        for (int c = 0; c < 64; c += 2) {
            float4 wa = __ldg((const float4*)&W1[c * 256 + j0]);
            float4 wb = __ldg((const float4*)&W1[(c + 1) * 256 + j0]);
            float2 va = *(const float2*)&v16[r0 * 64 + c];
            float2 vb = *(const float2*)&v16[(r0 + 1) * 64 + c];
            acc[0][0] += va.x * wa.x; acc[0][1] += va.x * wa.y;
            acc[0][2] += va.x * wa.z; acc[0][3] += va.x * wa.w;
            acc[1][0] += vb.x * wa.x; acc[1][1] += vb.x * wa.y;
            acc[1][2] += vb.x * wa.z; acc[1][3] += vb.x * wa.w;
            acc[0][0] += va.y * wb.x; acc[0][1] += va.y * wb.y;
            acc[0][2] += va.y * wb.z; acc[0][3] += va.y * wb.w;
            acc[1][0] += vb.y * wb.x; acc[1][1] += vb.y * wb.y;
            acc[1][2] += vb.y * wb.z; acc[1][3] += vb.y * wb.w;
        }
        float4 bv = __ldg((const float4*)&b1[j0]);
#pragma unroll
        for (int i = 0; i < 2; i++) {
            float4 s;
            s.x = gelu_f(acc[i][0] + bv.x);
            s.y = gelu_f(acc[i][1] + bv.y);
            s.z = gelu_f(acc[i][2] + bv.z);
            s.w = gelu_f(acc[i][3] + bv.w);
            *(float4*)&u16[(r0 + i) * 260 + j0] = s;
        }
    }
    __syncthreads();

    // 4) GEMM2 (16x256 @ 256x64): 2 rows x 4 cols per thread, 4-way k-split, k pairs.
    {
        const int kq = tid >> 7;             // 0..3
        const int t2 = tid & 127;
        const int r0 = (t2 >> 4) * 2;        // 0..14
        const int c0 = (t2 & 15) * 4;
        float acc[2][4];
#pragma unroll
        for (int i = 0; i < 2; i++)
#pragma unroll
            for (int j = 0; j < 4; j++) acc[i][j] = 0.f;
        const int jb = kq * 64;
#pragma unroll 4
        for (int jj = jb; jj < jb + 64; jj += 2) {
            float4 wa = __ldg((const float4*)&W2[jj * 64 + c0]);
            float4 wb = __ldg((const float4*)&W2[(jj + 1) * 64 + c0]);
            float2 ua = *(const float2*)&u16[r0 * 260 + jj];
            float2 ub = *(const float2*)&u16[(r0 + 1) * 260 + jj];
            acc[0][0] += ua.x * wa.x; acc[0][1] += ua.x * wa.y;
            acc[0][2] += ua.x * wa.z; acc[0][3] += ua.x * wa.w;
            acc[1][0] += ub.x * wa.x; acc[1][1] += ub.x * wa.y;
            acc[1][2] += ub.x * wa.z; acc[1][3] += ub.x * wa.w;
            acc[0][0] += ua.y * wb.x; acc[0][1] += ua.y * wb.y;
            acc[0][2] += ua.y * wb.z; acc[0][3] += ua.y * wb.w;
            acc[1][0] += ub.y * wb.x; acc[1][1] += ub.y * wb.y;
            acc[1][2] += ub.y * wb.z; acc[1][3] += ub.y * wb.w;
        }
#pragma unroll
        for (int i = 0; i < 2; i++) {
            float4 s = {acc[i][0], acc[i][1], acc[i][2], acc[i][3]};
            *(float4*)&pp[kq][(r0 + i) * 64 + c0] = s;
        }
    }
    __syncthreads();

    // 5) reduce kq partials + bias + residual: 512 float2, one per thread
    {
        float2 a = ((const float2*)pp[0])[tid];
        float2 b = ((const float2*)pp[1])[tid];
        float2 c = ((const float2*)pp[2])[tid];
        float2 d = ((const float2*)pp[3])[tid];
        float2 bb = __ldg(((const float2*)b2) + (tid & 31));
        float2 xr = __ldg(((const float2*)x) + m * 512 + tid);
        float2 r;
        r.x = a.x + b.x + c.x + d.x + bb.x + xr.x;
        r.y = a.y + b.y + c.y + d.y + bb.y + xr.y;
        ((float2*)out)[m * 512 + tid] = r;
    }
}

// ------------------------- launch ------------------------------------------------
extern "C" void kernel_launch(void* const* d_in, const int* in_sizes, int n_in,
                              void* d_out, int out_size) {
    const float* x   = (const float*)d_in[0];
    const float* kb  = (const float*)d_in[1];
    const float* fkb = (const float*)d_in[2];
    const float* Wsp = (const float*)d_in[3];
    const float* Wr  = (const float*)d_in[4];
    const float* cb  = (const float*)d_in[5];
    const float* lns = (const float*)d_in[6];
    const float* lnb = (const float*)d_in[7];
    const float* W1  = (const float*)d_in[8];
    const float* b1  = (const float*)d_in[9];
    const float* W2  = (const float*)d_in[10];
    const float* b2  = (const float*)d_in[11];
    float* out = (float*)d_out;

    cudaFuncSetAttribute(conv_kernel, cudaFuncAttributeMaxDynamicSharedMemorySize, SMEMSZ);

    conv_kernel<<<dim3(2, 16, 9), 512, SMEMSZ>>>(x, kb, Wsp, fkb, Wr);
    tail_kernel<<<256, 512>>>(x, cb, lns, lnb, W1, b1, W2, b2, out);
}

// round 17
// speedup vs baseline: 1.3647x; 1.3647x over previous
#include <cuda_runtime.h>
#include <cuda_fp16.h>
#include <cstdint>
#include <math.h>

// Problem: B=1, N=256, O=16, C=64, BASIS=32, WIDEN=4
// h[m,o,c] = sum_{n,s} kb[m,n,o,s] * x[n,o,c] * Ws[s,c]   (fp16 m16n8k16 mma, fp32 acc)
// then fiber conv over o with rk = fkb@Wr, +bias, LN, MLP(gelu), +x residual.
//
// R17: conv = R15 (measured best, ~34us); tail MLP moved to fp16 tensor cores
// (W1/W2 pre-transposed to half in conv's z==8 plane).

#define KS 8
#define NT 32
#define AST 40                    // A smem row stride (fp32 words)
#define BSTH 20                   // B smem row stride (half2 words)
#define NSTG 3                    // A pipeline stages
#define A_STAGE (128 * AST * 4)   // 20480 B per A stage (m-tile 128)
#define B_BUF   (64 * BSTH * 4)   // 5120 B per B buffer
#define B_OFF   (NSTG * A_STAGE)  // 61440
#define XS_OFF  (B_OFF + 2 * B_BUF)     // 71680
#define SMEMSZ  (XS_OFF + 4 * 64 * 4)   // 72704

__device__ float  g_rk[16 * 16 * 64];
__device__ float  g_h1[KS][256 * 16 * 64];
__device__ __half g_W1t[256 * 64];    // W1t[j][c] = W1[c][j]
__device__ __half g_W2t[64 * 256];    // W2t[n][k] = W2[k][n]

// ------------------------- helpers ------------------------------------------------
__device__ __forceinline__ uint32_t smem_u32(const void* p) {
    uint32_t a;
    asm("{ .reg .u64 t; cvta.to.shared.u64 t, %1; cvt.u32.u64 %0, t; }" : "=r"(a) : "l"(p));
    return a;
}
__device__ __forceinline__ void cpa16(uint32_t smemdst, const void* gsrc) {
    asm volatile("cp.async.cg.shared.global [%0], [%1], 16;" :: "r"(smemdst), "l"(gsrc));
}
__device__ __forceinline__ uint32_t packh2(float lo, float hi) {
    __half2 h = __floats2half2_rn(lo, hi);
    return *(uint32_t*)&h;
}
__device__ __forceinline__ void mma16(float* acc,
                                      uint32_t a0, uint32_t a1, uint32_t a2, uint32_t a3,
                                      uint32_t b0, uint32_t b1) {
    asm volatile(
        "mma.sync.aligned.m16n8k16.row.col.f32.f16.f16.f32 "
        "{%0,%1,%2,%3}, {%4,%5,%6,%7}, {%8,%9}, {%0,%1,%2,%3};"
        : "+f"(acc[0]), "+f"(acc[1]), "+f"(acc[2]), "+f"(acc[3])
        : "r"(a0), "r"(a1), "r"(a2), "r"(a3), "r"(b0), "r"(b1));
}
__device__ __forceinline__ float tanh_ap(float x) {
    float y;
    asm("tanh.approx.f32 %0, %1;" : "=f"(y) : "f"(x));
    return y;
}
__device__ __forceinline__ float gelu_f(float z) {
    float t = 0.7978845608028654f * (z + 0.044715f * z * z * z);
    return 0.5f * z * (1.0f + tanh_ap(t));
}

// ------------------------- kernel 1: big conv GEMM + folded prep ------------------
// grid (2, 16, 9): m-tile 128, o, k-split of 32 n-points; z==8: rotk + W transposes.
// Warp tiling m32 x n32. A: 3-stage cp.async (fp32), lookahead 2, wait_group 1.
__global__ __launch_bounds__(256, 3) void conv_kernel(const float* __restrict__ x,
                                                      const float* __restrict__ kb,
                                                      const float* __restrict__ Wsp,
                                                      const float* __restrict__ fkb,
                                                      const float* __restrict__ Wr,
                                                      const float* __restrict__ W1,
                                                      const float* __restrict__ W2) {
    if (blockIdx.z == 8) {
        int id = blockIdx.x * 16 + blockIdx.y;   // 0..31
        for (int idx = threadIdx.x; idx < 512; idx += 256) {
            int po = id * 8 + (idx >> 6), c = idx & 63;
            float acc = 0.f;
#pragma unroll
            for (int s = 0; s < 32; s++) acc += __ldg(&fkb[po * 32 + s]) * __ldg(&Wr[s * 64 + c]);
            g_rk[po * 64 + c] = acc;
        }
        for (int idx = threadIdx.x; idx < 512; idx += 256) {
            int j = id * 8 + (idx >> 6), c = idx & 63;
            g_W1t[j * 64 + c] = __float2half(__ldg(&W1[c * 256 + j]));
        }
        for (int idx = threadIdx.x; idx < 512; idx += 256) {
            int n = id * 2 + (idx >> 8), k = idx & 255;
            g_W2t[n * 256 + k] = __float2half(__ldg(&W2[k * 64 + n]));
        }
        return;
    }

    extern __shared__ char smem[];
    const uint32_t sbase = smem_u32(smem);
    float*    sA = (float*)smem;                 // [NSTG][128][AST] fp32
    uint32_t* sB = (uint32_t*)(smem + B_OFF);    // [2][64][BSTH] half2
    float*    xs = (float*)(smem + XS_OFF);      // [4][64] per-stage x rows

    const int tid  = threadIdx.x;
    const int w    = tid >> 5;
    const int lane = tid & 31;
    const int g    = lane >> 2;
    const int tq   = lane & 3;
    const int mw   = w >> 1;
    const int nw   = w & 1;
    const int m0   = blockIdx.x * 128;
    const int o    = blockIdx.y;
    const int ks   = blockIdx.z;
    const int n0   = ks * 32;

    auto prefetchA = [&](int t) {
        const int n = n0 + t;
        const uint32_t abase = sbase + (t % NSTG) * A_STAGE;
        const float* srcb = kb + (size_t)m0 * 131072 + (size_t)n * 512 + o * 32;
#pragma unroll
        for (int h = 0; h < 4; h++) {
            int q = tid + h * 256;
            int r = q >> 3, j = q & 7;
            cpa16(abase + (uint32_t)(r * AST + j * 4) * 4,
                  srcb + (size_t)r * 131072 + j * 4);
        }
    };
    auto prefetchX = [&](int t) {
        if (tid < 16)
            cpa16(sbase + XS_OFF + (t & 3) * 256 + tid * 16,
                  x + ((size_t)(n0 + t) * 16 + o) * 64 + tid * 4);
    };

    prefetchA(0); prefetchX(0); prefetchX(1);
    asm volatile("cp.async.commit_group;" ::: "memory");
    prefetchA(1); prefetchX(2);
    asm volatile("cp.async.commit_group;" ::: "memory");

    const int bc = tid >> 2, bq0 = (tid & 3) * 8;
    float ws[8];
#pragma unroll
    for (int i = 0; i < 8; i++) ws[i] = __ldg(&Wsp[(bq0 + i) * 64 + bc]);

    auto buildB = [&](int buf, int t) {
        float xv = xs[(t & 3) * 64 + bc];
        uint32_t* dst = &sB[buf * (64 * BSTH) + bc * BSTH + (bq0 >> 1)];
        uint2 v0, v1;
        v0.x = packh2(xv * ws[0], xv * ws[1]);
        v0.y = packh2(xv * ws[2], xv * ws[3]);
        v1.x = packh2(xv * ws[4], xv * ws[5]);
        v1.y = packh2(xv * ws[6], xv * ws[7]);
        *(uint2*)dst       = v0;
        *(uint2*)(dst + 2) = v1;
    };

    asm volatile("cp.async.wait_group 1;" ::: "memory");
    __syncthreads();
    buildB(0, 0);

    float acc[2][4][4];
#pragma unroll
    for (int mi = 0; mi < 2; mi++)
#pragma unroll
        for (int ni = 0; ni < 4; ni++)
#pragma unroll
            for (int i = 0; i < 4; i++) acc[mi][ni][i] = 0.f;

    for (int t = 0; t < NT; t++) {
        asm volatile("cp.async.wait_group 1;" ::: "memory");
        __syncthreads();

        if (t + 2 < NT) prefetchA(t + 2);
        if (t + 3 < NT) prefetchX(t + 3);
        asm volatile("cp.async.commit_group;" ::: "memory");
        if (t + 1 < NT) buildB((t + 1) & 1, t + 1);

        const float*    At  = sA + (t % NSTG) * (128 * AST);
        const uint32_t* BTh = sB + (t & 1) * (64 * BSTH);
#pragma unroll
        for (int step = 0; step < 2; step++) {
            const int k0 = step * 16;
            uint32_t af[2][4];
#pragma unroll
            for (int mi = 0; mi < 2; mi++) {
                const float* rp0 = &At[(mw * 32 + mi * 16 + g) * AST + k0 + 2 * tq];
                const float* rp1 = rp0 + 8 * AST;
                float2 p0 = *(const float2*)rp0;
                float2 p1 = *(const float2*)rp1;
                float2 p2 = *(const float2*)(rp0 + 8);
                float2 p3 = *(const float2*)(rp1 + 8);
                af[mi][0] = packh2(p0.x, p0.y);
                af[mi][1] = packh2(p1.x, p1.y);
                af[mi][2] = packh2(p2.x, p2.y);
                af[mi][3] = packh2(p3.x, p3.y);
            }
#pragma unroll
            for (int ni = 0; ni < 4; ni++) {
                const int col = nw * 32 + ni * 8 + g;
                uint32_t b0 = BTh[col * BSTH + (k0 >> 1) + tq];
                uint32_t b1 = BTh[col * BSTH + (k0 >> 1) + tq + 4];
                mma16(acc[0][ni], af[0][0], af[0][1], af[0][2], af[0][3], b0, b1);
                mma16(acc[1][ni], af[1][0], af[1][1], af[1][2], af[1][3], b0, b1);
            }
        }
    }

#pragma unroll
    for (int mi = 0; mi < 2; mi++) {
        const int mr = m0 + mw * 32 + mi * 16 + g;
        float* dst0 = g_h1[ks] + ((size_t)mr * 16 + o) * 64 + nw * 32 + 2 * tq;
        float* dst1 = dst0 + (size_t)8 * 16 * 64;
#pragma unroll
        for (int ni = 0; ni < 4; ni++) {
            float2 v0 = {acc[mi][ni][0], acc[mi][ni][1]};
            float2 v1 = {acc[mi][ni][2], acc[mi][ni][3]};
            *(float2*)(dst0 + ni * 8) = v0;
            *(float2*)(dst1 + ni * 8) = v1;
        }
    }
}

// ------------------------- kernel 2: fused tail (grid 256 x 512, mma MLP) ---------
// one block per m (16 p-rows). partial-sum + fiber conv + LN + fp16-mma MLP + resid.
__global__ __launch_bounds__(512) void tail_kernel(const float* __restrict__ x,
                                                   const float* __restrict__ cb,
                                                   const float* __restrict__ lns,
                                                   const float* __restrict__ lnb,
                                                   const float* __restrict__ b1,
                                                   const float* __restrict__ b2,
                                                   float* __restrict__ out) {
    __shared__ __align__(16) float  hs[1024];        // summed conv [16 o][64 c]
    __shared__ __align__(16) __half vh[16 * 72];     // post-LN rows (half, padded)
    __shared__ __align__(16) __half uh[16 * 264];    // hidden (half, padded)
    __shared__ __align__(16) float  pp[2][16 * 66];  // GEMM2 partials (padded)

    const int tid = threadIdx.x;
    const int m   = blockIdx.x;

    // 1) sum KS k-split partials: 512 float2, one per thread
    {
        float2 a = ((const float2*)g_h1[0])[m * 512 + tid];
#pragma unroll
        for (int q = 1; q < KS; q++) {
            float2 b = ((const float2*)g_h1[q])[m * 512 + tid];
            a.x += b.x; a.y += b.y;
        }
        ((float2*)hs)[tid] = a;
    }
    __syncthreads();

    // 2) fiber conv + bias + LN; one warp per row (p = tid>>5), 2 channels/lane
    {
        const int p  = tid >> 5;          // 0..15
        const int l  = tid & 31;
        const int c0 = l * 2;
        float2 hv;
        hv.x = __ldg(&cb[c0]);
        hv.y = __ldg(&cb[c0 + 1]);
#pragma unroll
        for (int oo = 0; oo < 16; oo++) {
            float2 h2 = *(const float2*)&hs[oo * 64 + c0];
            float2 r2 = __ldg((const float2*)&g_rk[(p * 16 + oo) * 64 + c0]);
            hv.x += h2.x * r2.x;
            hv.y += h2.y * r2.y;
        }
        float s = hv.x + hv.y;
#pragma unroll
        for (int d = 1; d < 32; d <<= 1) s += __shfl_xor_sync(0xffffffffu, s, d);
        float mu = s * (1.f / 64.f);
        float d0 = hv.x - mu, d1 = hv.y - mu;
        float ss = d0 * d0 + d1 * d1;
#pragma unroll
        for (int d = 1; d < 32; d <<= 1) ss += __shfl_xor_sync(0xffffffffu, ss, d);
        float rs = rsqrtf(ss * (1.f / 64.f) + 1e-6f);
        float ovx = d0 * rs * __ldg(&lns[c0])     + __ldg(&lnb[c0]);
        float ovy = d1 * rs * __ldg(&lns[c0 + 1]) + __ldg(&lnb[c0 + 1]);
        *(uint32_t*)&vh[p * 72 + c0] = packh2(ovx, ovy);
    }
    __syncthreads();

    const int w    = tid >> 5;
    const int lane = tid & 31;
    const int g    = lane >> 2;
    const int tq   = lane & 3;

    // 3) GEMM1 (16x64 @ 64x256) + gelu, fp16 mma: warp w owns col-blocks 2w, 2w+1.
    {
        float acc[2][4];
#pragma unroll
        for (int i = 0; i < 2; i++)
#pragma unroll
            for (int j = 0; j < 4; j++) acc[i][j] = 0.f;
#pragma unroll
        for (int kk = 0; kk < 4; kk++) {
            const int k0 = kk * 16;
            const __half* vp = &vh[g * 72 + k0 + 2 * tq];
            uint32_t a0 = *(const uint32_t*)vp;
            uint32_t a1 = *(const uint32_t*)(vp + 8 * 72);
            uint32_t a2 = *(const uint32_t*)(vp + 8);
            uint32_t a3 = *(const uint32_t*)(vp + 8 * 72 + 8);
#pragma unroll
            for (int cbi = 0; cbi < 2; cbi++) {
                const int cb = w * 2 + cbi;
                const __half* wp = &g_W1t[(cb * 8 + g) * 64 + k0 + 2 * tq];
                uint32_t b0 = *(const uint32_t*)wp;
                uint32_t br = *(const uint32_t*)(wp + 8);
                mma16(acc[cbi], a0, a1, a2, a3, b0, br);
            }
        }
#pragma unroll
        for (int cbi = 0; cbi < 2; cbi++) {
            const int col = (w * 2 + cbi) * 8 + 2 * tq;
            float2 bv = __ldg((const float2*)&b1[col]);
            float s0 = gelu_f(acc[cbi][0] + bv.x);
            float s1 = gelu_f(acc[cbi][1] + bv.y);
            float s2 = gelu_f(acc[cbi][2] + bv.x);
            float s3 = gelu_f(acc[cbi][3] + bv.y);
            *(uint32_t*)&uh[g * 264 + col]       = packh2(s0, s1);
            *(uint32_t*)&uh[(g + 8) * 264 + col] = packh2(s2, s3);
        }
    }
    __syncthreads();

    // 4) GEMM2 (16x256 @ 256x64), fp16 mma: kh = w>>3 half of K, cb2 = w&7 col-block.
    {
        const int kh  = w >> 3;
        const int cb2 = w & 7;
        float acc[4] = {0.f, 0.f, 0.f, 0.f};
#pragma unroll
        for (int kk = 0; kk < 8; kk++) {
            const int k0 = (kh * 8 + kk) * 16;
            const __half* up = &uh[g * 264 + k0 + 2 * tq];
            uint32_t a0 = *(const uint32_t*)up;
            uint32_t a1 = *(const uint32_t*)(up + 8 * 264);
            uint32_t a2 = *(const uint32_t*)(up + 8);
            uint32_t a3 = *(const uint32_t*)(up + 8 * 264 + 8);
            const __half* wp = &g_W2t[(cb2 * 8 + g) * 256 + k0 + 2 * tq];
            uint32_t b0 = *(const uint32_t*)wp;
            uint32_t br = *(const uint32_t*)(wp + 8);
            mma16(acc, a0, a1, a2, a3, b0, br);
        }
        const int col = cb2 * 8 + 2 * tq;
        *(float2*)&pp[kh][g * 66 + col]       = make_float2(acc[0], acc[1]);
        *(float2*)&pp[kh][(g + 8) * 66 + col] = make_float2(acc[2], acc[3]);
    }
    __syncthreads();

    // 5) reduce 2 k-halves + bias + residual: 512 float2, one per thread
    {
        const int row = tid >> 5;
        const int cp  = tid & 31;
        float2 a = *(const float2*)&pp[0][row * 66 + cp * 2];
        float2 b = *(const float2*)&pp[1][row * 66 + cp * 2];
        float2 bb = __ldg(((const float2*)b2) + cp);
        float2 xr = __ldg(((const float2*)x) + m * 512 + tid);
        float2 r;
        r.x = a.x + b.x + bb.x + xr.x;
        r.y = a.y + b.y + bb.y + xr.y;
        ((float2*)out)[m * 512 + tid] = r;
    }
}

// ------------------------- launch ------------------------------------------------
extern "C" void kernel_launch(void* const* d_in, const int* in_sizes, int n_in,
                              void* d_out, int out_size) {
    const float* x   = (const float*)d_in[0];
    const float* kb  = (const float*)d_in[1];
    const float* fkb = (const float*)d_in[2];
    const float* Wsp = (const float*)d_in[3];
    const float* Wr  = (const float*)d_in[4];
    const float* cb  = (const float*)d_in[5];
    const float* lns = (const float*)d_in[6];
    const float* lnb = (const float*)d_in[7];
    const float* W1  = (const float*)d_in[8];
    const float* b1  = (const float*)d_in[9];
    const float* W2  = (const float*)d_in[10];
    const float* b2  = (const float*)d_in[11];
    float* out = (float*)d_out;

    cudaFuncSetAttribute(conv_kernel, cudaFuncAttributeMaxDynamicSharedMemorySize, SMEMSZ);

    conv_kernel<<<dim3(2, 16, 9), 256, SMEMSZ>>>(x, kb, Wsp, fkb, Wr, W1, W2);
    tail_kernel<<<256, 512>>>(x, cb, lns, lnb, b1, b2, out);
}